// round 3
// baseline (speedup 1.0000x reference)
#include <cuda_runtime.h>
#include <cstdint>
#include <cstddef>

// ---------------- problem constants ----------------
#define BB   16
#define NNq  1024
#define DD   768
#define HH   12
#define HDD  64
#define PP   16
#define FFF  3072
#define MTOK (BB*NNq)     // 16384
#define LL   (PP+NNq)     // 1040
#define BHh  (BB*HH)      // 192

// ---------------- scratch (device globals; no allocation) ----------------
__device__ float g_h [MTOK*DD];        // LN output (h1 then h2)
__device__ float g_q [BHh*NNq*HDD];    // [b,h,t,hd]
__device__ float g_k [BHh*LL*HDD];     // [b,h,P+t,hd]
__device__ float g_vt[BHh*HDD*LL];     // [b,h,hd,P+t] (V transposed)
__device__ float g_o [MTOK*DD];        // attn out [b,t, h*64+hd]
__device__ float g_x1[MTOK*DD];        // residual 1
__device__ float g_m [MTOK*FFF];       // MLP hidden

// buffer selectors (0 = use passed pointer)
template<int SEL>
__device__ __forceinline__ float* buf_ptr(const void* arg) {
    if (SEL == 1) return g_h;
    if (SEL == 2) return g_o;
    if (SEL == 3) return g_x1;
    if (SEL == 4) return g_m;
    return (float*)arg;
}

// ---------------- async-copy helpers ----------------
__device__ __forceinline__ void cp16(uint32_t d, const void* s) {
    asm volatile("cp.async.ca.shared.global [%0], [%1], 16;\n" :: "r"(d), "l"(s));
}
__device__ __forceinline__ void cp16z(uint32_t d, const void* s, int sz) {
    asm volatile("cp.async.ca.shared.global [%0], [%1], 16, %2;\n" :: "r"(d), "l"(s), "r"(sz));
}
__device__ __forceinline__ void cp_commit() { asm volatile("cp.async.commit_group;\n" ::: "memory"); }
__device__ __forceinline__ void cp_wait0()  { asm volatile("cp.async.wait_group 0;\n" ::: "memory"); }

__device__ __forceinline__ void mma_tf32(float c[4], const uint32_t a[4], const uint32_t b[2]) {
    asm volatile(
        "mma.sync.aligned.m16n8k8.row.col.f32.tf32.tf32.f32 "
        "{%0,%1,%2,%3},{%4,%5,%6,%7},{%8,%9},{%0,%1,%2,%3};\n"
        : "+f"(c[0]), "+f"(c[1]), "+f"(c[2]), "+f"(c[3])
        : "r"(a[0]), "r"(a[1]), "r"(a[2]), "r"(a[3]), "r"(b[0]), "r"(b[1]));
}

// ---------------- epilogues ----------------
// 0: QKV scatter (+bias) into g_q / g_k / g_vt
// 3: +bias +res -> out (ldc = DD)
// 4: +bias, QuickGELU -> out (ldc = FFF)
template<int EPI>
__device__ __forceinline__ void do_epi(int r, int c, float v,
                                       const float* __restrict__ bias,
                                       const float* __restrict__ res,
                                       float* __restrict__ out)
{
    if (EPI == 0) {
        v += bias[c];
        int which = c / DD;
        int d = c - which * DD;
        int h = d >> 6, hd = d & 63;
        int b = r >> 10, t = r & 1023;
        int bh = b * HH + h;
        if (which == 0)      g_q [(((size_t)bh << 10) + t) * HDD + hd] = v;
        else if (which == 1) g_k [((size_t)bh * LL + PP + t) * HDD + hd] = v;
        else                 g_vt[((size_t)bh * HDD + hd) * LL + PP + t] = v;
    } else if (EPI == 3) {
        size_t o = (size_t)r * DD + c;
        out[o] = v + bias[c] + res[o];
    } else { // 4
        v += bias[c];
        out[(size_t)r * FFF + c] = v / (1.f + __expf(-1.702f * v));
    }
}

// swizzled smem index for a 16-float-wide tile row
__device__ __forceinline__ int sidx16(int r, int c) {
    return r * 16 + ((((c >> 2) ^ ((r >> 1) & 3))) << 2) + (c & 3);
}

// ---------------- NT GEMM: C = A[M,K] * B[N,K]^T, tf32 mma, cp.async double buffer ----------------
// BM=BN=128, BK=16. 256 threads = 8 warps (4m x 2n), warp tile 32x64.
template<int EPI, int ASEL, int RSEL, int OSEL>
__global__ __launch_bounds__(256)
void gemm_nt(const float* __restrict__ Aarg, int lda,
             const float* __restrict__ B, int ldb, int K,
             const float* __restrict__ bias,
             const float* __restrict__ resarg,
             float* __restrict__ outarg)
{
    __shared__ uint32_t As[2][2048];   // 128 x 16, swizzled
    __shared__ uint32_t Bs[2][2048];

    const float* A   = buf_ptr<ASEL>(Aarg);
    const float* res = buf_ptr<RSEL>(resarg);
    float*       out = buf_ptr<OSEL>(outarg);

    const int tid  = threadIdx.x;
    const int lane = tid & 31, wid = tid >> 5;
    const int warpM = wid >> 1, warpN = wid & 1;
    const int g = lane >> 2, tg = lane & 3;
    const int m0 = blockIdx.y * 128, n0 = blockIdx.x * 128;

    const uint32_t sA = (uint32_t)__cvta_generic_to_shared(&As[0][0]);
    const uint32_t sB = (uint32_t)__cvta_generic_to_shared(&Bs[0][0]);

    // per-thread load coords: 512 float4 per tile, 2 per thread (rows lr, lr+64)
    const int lr  = tid >> 2;
    const int lg  = tid & 3;
    const int lsg = lg ^ ((lr >> 1) & 3);           // same for row lr+64 (64>>1 = 32, &3 = 0)
    const uint32_t aoff = (uint32_t)(lr * 16 + lsg * 4) * 4;

    float acc[2][8][4];
    #pragma unroll
    for (int mt = 0; mt < 2; mt++)
        #pragma unroll
        for (int nt = 0; nt < 8; nt++)
            #pragma unroll
            for (int i = 0; i < 4; i++) acc[mt][nt][i] = 0.f;

    const int chunks = K >> 4;

    // prologue: stage 0
    #pragma unroll
    for (int i = 0; i < 2; i++) {
        cp16(sA + aoff + (uint32_t)(i * 64 * 16) * 4,
             A + (size_t)(m0 + lr + i * 64) * lda + lg * 4);
        cp16(sB + aoff + (uint32_t)(i * 64 * 16) * 4,
             B + (size_t)(n0 + lr + i * 64) * ldb + lg * 4);
    }
    cp_commit();

    int buf = 0;
    for (int c = 0; c < chunks; c++) {
        cp_wait0();
        __syncthreads();
        if (c + 1 < chunks) {
            const int k0 = (c + 1) << 4;
            const uint32_t so = (uint32_t)((buf ^ 1) * 2048) * 4;
            #pragma unroll
            for (int i = 0; i < 2; i++) {
                cp16(sA + so + aoff + (uint32_t)(i * 64 * 16) * 4,
                     A + (size_t)(m0 + lr + i * 64) * lda + k0 + lg * 4);
                cp16(sB + so + aoff + (uint32_t)(i * 64 * 16) * 4,
                     B + (size_t)(n0 + lr + i * 64) * ldb + k0 + lg * 4);
            }
            cp_commit();
        } else {
            cp_commit();   // keep group accounting uniform
        }

        const uint32_t* as = As[buf];
        const uint32_t* bs = Bs[buf];
        #pragma unroll
        for (int ks = 0; ks < 2; ks++) {
            const int kk = ks * 8;
            uint32_t a[2][4], b[8][2];
            #pragma unroll
            for (int mt = 0; mt < 2; mt++) {
                int rb = warpM * 32 + mt * 16 + g;
                a[mt][0] = as[sidx16(rb,     kk + tg)];
                a[mt][1] = as[sidx16(rb + 8, kk + tg)];
                a[mt][2] = as[sidx16(rb,     kk + tg + 4)];
                a[mt][3] = as[sidx16(rb + 8, kk + tg + 4)];
            }
            #pragma unroll
            for (int nt = 0; nt < 8; nt++) {
                int cb = warpN * 64 + nt * 8 + g;
                b[nt][0] = bs[sidx16(cb, kk + tg)];
                b[nt][1] = bs[sidx16(cb, kk + tg + 4)];
            }
            #pragma unroll
            for (int mt = 0; mt < 2; mt++)
                #pragma unroll
                for (int nt = 0; nt < 8; nt++)
                    mma_tf32(acc[mt][nt], a[mt], b[nt]);
        }
        buf ^= 1;
    }

    // epilogue (all dims are multiples of tile sizes — no guards)
    #pragma unroll
    for (int mt = 0; mt < 2; mt++) {
        #pragma unroll
        for (int nt = 0; nt < 8; nt++) {
            int r0 = m0 + warpM * 32 + mt * 16 + g;
            int c0 = n0 + warpN * 64 + nt * 8 + tg * 2;
            #pragma unroll
            for (int i = 0; i < 4; i++) {
                int r = r0 + (i >> 1) * 8;
                int c = c0 + (i & 1);
                do_epi<EPI>(r, c, acc[mt][nt][i], bias, res, out);
            }
        }
    }
}

// ---------------- fused flash attention (32-key tiles, cp.async double buffer) ----------------
// grid (8, 192): x = 128-query tile, y = b*H+h. 8 warps, 16 q-rows each.
#define FTILES 33          // ceil(1040/32)
__global__ __launch_bounds__(256)
void flash_kernel()
{
    __shared__ uint32_t Ks[2][32 * 64];   // [key][hd]
    __shared__ uint32_t Vs[2][64 * 32];   // [hd][key]

    const int tid = threadIdx.x, lane = tid & 31, wid = tid >> 5;
    const int g = lane >> 2, tg = lane & 3;
    const int m0 = blockIdx.x * 128;
    const int bh = blockIdx.y;
    const int b = bh / HH, h = bh - b * HH;
    const int wb = wid * 16;

    const uint32_t sK = (uint32_t)__cvta_generic_to_shared(&Ks[0][0]);
    const uint32_t sV = (uint32_t)__cvta_generic_to_shared(&Vs[0][0]);

    // per-thread cp.async coords (512 float4 per tile, 2 per thread)
    // K: rows 0..31 (16 groups/row); V: rows 0..63 (8 groups/row)
    // Q fragments straight from gmem (bit-truncated tf32)
    uint32_t qf[8][4];
    {
        const float* Q1 = g_q + ((size_t)bh * NNq + m0 + wb + g) * HDD;
        const float* Q2 = Q1 + 8 * HDD;
        #pragma unroll
        for (int kt = 0; kt < 8; kt++) {
            qf[kt][0] = __float_as_uint(Q1[kt * 8 + tg]);
            qf[kt][1] = __float_as_uint(Q2[kt * 8 + tg]);
            qf[kt][2] = __float_as_uint(Q1[kt * 8 + tg + 4]);
            qf[kt][3] = __float_as_uint(Q2[kt * 8 + tg + 4]);
        }
    }

    float m1 = -1e30f, m2 = -1e30f, l1 = 0.f, l2 = 0.f;
    float oacc[8][4];
    #pragma unroll
    for (int nt = 0; nt < 8; nt++)
        #pragma unroll
        for (int i = 0; i < 4; i++) oacc[nt][i] = 0.f;

    // ---- tile loader ----
    auto issue_tile = [&](int t, int s) {
        const int kb = t * 32;
        const uint32_t soff = (uint32_t)(s * 2048) * 4;
        #pragma unroll
        for (int i = 0; i < 2; i++) {
            int idx = tid + i * 256;
            // K slice
            int kr = idx >> 4, kg = idx & 15;
            int ksg = kg ^ (kr & 7);
            int krow = kb + kr; if (krow >= LL) krow = LL - 1;
            cp16z(sK + soff + (uint32_t)(kr * 64 + ksg * 4) * 4,
                  g_k + ((size_t)bh * LL + krow) * HDD + kg * 4,
                  (kb + kr) < LL ? 16 : 0);
            // V slice
            int vr = idx >> 3, vg = idx & 7;
            int vsg = vg ^ (vr & 7);
            cp16z(sV + soff + (uint32_t)(vr * 32 + vsg * 4) * 4,
                  g_vt + ((size_t)bh * HDD + vr) * LL + kb + vg * 4,
                  (kb + vg * 4 + 4) <= LL ? 16 : 0);
        }
    };

    issue_tile(0, 0);
    cp_commit();

    int buf = 0;
    for (int t = 0; t < FTILES; t++) {
        const int kb = t * 32;
        cp_wait0();
        __syncthreads();
        if (t + 1 < FTILES) { issue_tile(t + 1, buf ^ 1); cp_commit(); }
        else                { cp_commit(); }

        const uint32_t* ks_ = Ks[buf];
        const uint32_t* vs_ = Vs[buf];

        // S = Q K^T  (per-warp 16 x 32)
        float s[4][4];
        #pragma unroll
        for (int nt = 0; nt < 4; nt++)
            #pragma unroll
            for (int i = 0; i < 4; i++) s[nt][i] = 0.f;
        #pragma unroll
        for (int kt = 0; kt < 8; kt++) {
            #pragma unroll
            for (int nt = 0; nt < 4; nt++) {
                int row = nt * 8 + g;
                uint32_t bf[2];
                int c0 = kt * 8 + tg;
                bf[0] = ks_[row * 64 + (((c0 >> 2) ^ (row & 7)) << 2) + tg];
                int c1 = c0 + 4;
                bf[1] = ks_[row * 64 + (((c1 >> 2) ^ (row & 7)) << 2) + tg];
                mma_tf32(s[nt], qf[kt], bf);
            }
        }

        // scale + mask + online softmax
        float mx1 = -1e30f, mx2 = -1e30f;
        #pragma unroll
        for (int nt = 0; nt < 4; nt++) {
            int col = kb + nt * 8 + tg * 2;
            #pragma unroll
            for (int i = 0; i < 4; i++) s[nt][i] *= 0.125f;
            if (col >= LL)     { s[nt][0] = -1e30f; s[nt][2] = -1e30f; }
            if (col + 1 >= LL) { s[nt][1] = -1e30f; s[nt][3] = -1e30f; }
            mx1 = fmaxf(mx1, fmaxf(s[nt][0], s[nt][1]));
            mx2 = fmaxf(mx2, fmaxf(s[nt][2], s[nt][3]));
        }
        #pragma unroll
        for (int o = 1; o <= 2; o <<= 1) {
            mx1 = fmaxf(mx1, __shfl_xor_sync(0xffffffffu, mx1, o));
            mx2 = fmaxf(mx2, __shfl_xor_sync(0xffffffffu, mx2, o));
        }
        const float nm1 = fmaxf(m1, mx1), nm2 = fmaxf(m2, mx2);
        const float f1 = __expf(m1 - nm1), f2 = __expf(m2 - nm2);
        float sum1 = 0.f, sum2 = 0.f;
        #pragma unroll
        for (int nt = 0; nt < 4; nt++) {
            s[nt][0] = __expf(s[nt][0] - nm1); sum1 += s[nt][0];
            s[nt][1] = __expf(s[nt][1] - nm1); sum1 += s[nt][1];
            s[nt][2] = __expf(s[nt][2] - nm2); sum2 += s[nt][2];
            s[nt][3] = __expf(s[nt][3] - nm2); sum2 += s[nt][3];
        }
        #pragma unroll
        for (int o = 1; o <= 2; o <<= 1) {
            sum1 += __shfl_xor_sync(0xffffffffu, sum1, o);
            sum2 += __shfl_xor_sync(0xffffffffu, sum2, o);
        }
        l1 = l1 * f1 + sum1; m1 = nm1;
        l2 = l2 * f2 + sum2; m2 = nm2;
        #pragma unroll
        for (int nt = 0; nt < 8; nt++) {
            oacc[nt][0] *= f1; oacc[nt][1] *= f1;
            oacc[nt][2] *= f2; oacc[nt][3] *= f2;
        }

        // P * V : C-fragment -> A-fragment via shuffles (4 k8 chunks)
        const int src_a = g * 4 + (tg >> 1);
        const int src_b = src_a + 2;
        const int sel = tg & 1;
        #pragma unroll
        for (int kt = 0; kt < 4; kt++) {
            uint32_t p0 = __float_as_uint(s[kt][0]);
            uint32_t p1 = __float_as_uint(s[kt][1]);
            uint32_t p2 = __float_as_uint(s[kt][2]);
            uint32_t p3 = __float_as_uint(s[kt][3]);
            uint32_t x0 = __shfl_sync(0xffffffffu, p0, src_a);
            uint32_t x1 = __shfl_sync(0xffffffffu, p1, src_a);
            uint32_t x2 = __shfl_sync(0xffffffffu, p2, src_a);
            uint32_t x3 = __shfl_sync(0xffffffffu, p3, src_a);
            uint32_t y0 = __shfl_sync(0xffffffffu, p0, src_b);
            uint32_t y1 = __shfl_sync(0xffffffffu, p1, src_b);
            uint32_t y2 = __shfl_sync(0xffffffffu, p2, src_b);
            uint32_t y3 = __shfl_sync(0xffffffffu, p3, src_b);
            uint32_t af[4];
            af[0] = sel ? x1 : x0;
            af[1] = sel ? x3 : x2;
            af[2] = sel ? y1 : y0;
            af[3] = sel ? y3 : y2;
            #pragma unroll
            for (int nt = 0; nt < 8; nt++) {
                int row = nt * 8 + g;
                uint32_t bf[2];
                int c0 = kt * 8 + tg;
                bf[0] = vs_[row * 32 + (((c0 >> 2) ^ (row & 7)) << 2) + tg];
                int c1 = c0 + 4;
                bf[1] = vs_[row * 32 + (((c1 >> 2) ^ (row & 7)) << 2) + tg];
                mma_tf32(oacc[nt], af, bf);
            }
        }
        buf ^= 1;
    }

    // epilogue: normalize and store to g_o [b,t, h*64+hd]
    const float inv1 = 1.f / l1, inv2 = 1.f / l2;
    float* O1 = g_o + ((size_t)(b * NNq) + m0 + wb + g) * DD + h * HDD;
    float* O2 = O1 + 8 * DD;
    #pragma unroll
    for (int nt = 0; nt < 8; nt++) {
        int c = nt * 8 + tg * 2;
        O1[c]     = oacc[nt][0] * inv1;
        O1[c + 1] = oacc[nt][1] * inv1;
        O2[c]     = oacc[nt][2] * inv2;
        O2[c + 1] = oacc[nt][3] * inv2;
    }
}

// ---------------- LayerNorm (one block per token; out -> g_h) ----------------
template<int XSEL>
__global__ __launch_bounds__(256)
void ln_kernel(const float* __restrict__ xarg, const float* __restrict__ gw,
               const float* __restrict__ bw)
{
    __shared__ float red[2][8];
    __shared__ float s_mu, s_rstd;
    const float* x = buf_ptr<XSEL>(xarg);
    const int row = blockIdx.x;
    const float* xr = x + (size_t)row * DD;
    float* orow = g_h + (size_t)row * DD;
    const int tid = threadIdx.x;

    float lv[3];
    float s = 0.f, s2 = 0.f;
    #pragma unroll
    for (int i = 0; i < 3; i++) {
        float v = xr[tid + i * 256];
        lv[i] = v; s += v; s2 += v * v;
    }
    #pragma unroll
    for (int o = 16; o; o >>= 1) {
        s  += __shfl_xor_sync(0xffffffffu, s,  o);
        s2 += __shfl_xor_sync(0xffffffffu, s2, o);
    }
    if ((tid & 31) == 0) { red[0][tid >> 5] = s; red[1][tid >> 5] = s2; }
    __syncthreads();
    if (tid == 0) {
        float ts = 0.f, ts2 = 0.f;
        #pragma unroll
        for (int i = 0; i < 8; i++) { ts += red[0][i]; ts2 += red[1][i]; }
        float mu = ts * (1.f / 768.f);
        float var = ts2 * (1.f / 768.f) - mu * mu;
        s_mu = mu; s_rstd = rsqrtf(var + 1e-5f);
    }
    __syncthreads();
    const float mu = s_mu, rstd = s_rstd;
    #pragma unroll
    for (int i = 0; i < 3; i++) {
        int c = tid + i * 256;
        orow[c] = (lv[i] - mu) * rstd * gw[c] + bw[c];
    }
}

// ---------------- prompt scatter: prompt[B,2,P,H,HD] -> g_k / g_vt ----------------
__global__ __launch_bounds__(256)
void prompt_copy(const float* __restrict__ pr)
{
    int idx = blockIdx.x * 256 + threadIdx.x;
    if (idx >= BB * 2 * PP * HH * HDD) return;
    float v = pr[idx];
    int hd = idx & 63; int t = idx >> 6;
    int h = t % HH;    t /= HH;
    int p = t % PP;    t /= PP;
    int kv = t & 1;    int b = t >> 1;
    int bh = b * HH + h;
    if (kv == 0) g_k [((size_t)bh * LL + p) * HDD + hd] = v;
    else         g_vt[((size_t)bh * HDD + hd) * LL + p] = v;
}

// ---------------- launcher (kernel launches ONLY) ----------------
extern "C" void kernel_launch(void* const* d_in, const int* in_sizes, int n_in,
                              void* d_out, int out_size)
{
    const float* x      = (const float*)d_in[0];
    const float* prompt = (const float*)d_in[1];
    const float* qkv_w  = (const float*)d_in[2];
    const float* qkv_b  = (const float*)d_in[3];
    const float* out_w  = (const float*)d_in[4];
    const float* out_b  = (const float*)d_in[5];
    const float* ln1_g  = (const float*)d_in[6];
    const float* ln1_b  = (const float*)d_in[7];
    const float* ln2_g  = (const float*)d_in[8];
    const float* ln2_b  = (const float*)d_in[9];
    const float* fc1_w  = (const float*)d_in[10];
    const float* fc1_b  = (const float*)d_in[11];
    const float* fc2_w  = (const float*)d_in[12];
    const float* fc2_b  = (const float*)d_in[13];
    float* outp = (float*)d_out;

    // 1. prompt scatter into K / V^T caches
    prompt_copy<<<(BB * 2 * PP * HH * HDD + 255) / 256, 256>>>(prompt);
    // 2. LN1: x -> g_h
    ln_kernel<0><<<MTOK, 256>>>(x, ln1_g, ln1_b);
    // 3. QKV GEMM + scatter into g_q / g_k / g_vt
    gemm_nt<0, 1, 0, 0><<<dim3(18, 128), 256>>>(
        nullptr, DD, qkv_w, DD, DD, qkv_b, nullptr, nullptr);
    // 4. fused flash attention -> g_o
    flash_kernel<<<dim3(8, BHh), 256>>>();
    // 5. out-proj + bias + residual(x) -> g_x1
    gemm_nt<3, 2, 0, 3><<<dim3(6, 128), 256>>>(
        nullptr, DD, out_w, DD, DD, out_b, x, nullptr);
    // 6. LN2: g_x1 -> g_h
    ln_kernel<3><<<MTOK, 256>>>(nullptr, ln2_g, ln2_b);
    // 7. FC1 + bias + QuickGELU -> g_m
    gemm_nt<4, 1, 0, 4><<<dim3(24, 128), 256>>>(
        nullptr, DD, fc1_w, DD, DD, fc1_b, nullptr, nullptr);
    // 8. FC2 + bias + residual(g_x1) -> d_out
    gemm_nt<3, 4, 3, 0><<<dim3(6, 128), 256>>>(
        nullptr, FFF, fc2_w, FFF, FFF, fc2_b, nullptr, outp);
}

// round 5
// speedup vs baseline: 1.3270x; 1.3270x over previous
#include <cuda_runtime.h>
#include <cstdint>
#include <cstddef>

// ---------------- problem constants ----------------
#define BB   16
#define NNq  1024
#define DD   768
#define HH   12
#define HDD  64
#define PP   16
#define FFF  3072
#define MTOK (BB*NNq)     // 16384
#define LL   (PP+NNq)     // 1040
#define BHh  (BB*HH)      // 192

// ---------------- scratch (device globals; no allocation) ----------------
__device__ float g_h [MTOK*DD];        // LN output (h1 then h2)
__device__ float g_q [BHh*NNq*HDD];    // [b,h,t,hd]
__device__ float g_k [BHh*LL*HDD];     // [b,h,P+t,hd]
__device__ float g_vt[BHh*HDD*LL];     // [b,h,hd,P+t] (V transposed)
__device__ float g_o [MTOK*DD];        // attn out [b,t, h*64+hd]
__device__ float g_x1[MTOK*DD];        // residual 1
__device__ float g_m [MTOK*FFF];       // MLP hidden

// buffer selectors (0 = use passed pointer)
template<int SEL>
__device__ __forceinline__ float* buf_ptr(const void* arg) {
    if (SEL == 1) return g_h;
    if (SEL == 2) return g_o;
    if (SEL == 3) return g_x1;
    if (SEL == 4) return g_m;
    return (float*)arg;
}

// ---------------- async-copy helpers ----------------
__device__ __forceinline__ void cp16(uint32_t d, const void* s) {
    asm volatile("cp.async.cg.shared.global [%0], [%1], 16;\n" :: "r"(d), "l"(s));
}
__device__ __forceinline__ void cp16z(uint32_t d, const void* s, int sz) {
    asm volatile("cp.async.cg.shared.global [%0], [%1], 16, %2;\n" :: "r"(d), "l"(s), "r"(sz));
}
__device__ __forceinline__ void cp_commit() { asm volatile("cp.async.commit_group;\n" ::: "memory"); }
__device__ __forceinline__ void cp_wait1()  { asm volatile("cp.async.wait_group 1;\n" ::: "memory"); }

__device__ __forceinline__ void mma_tf32(float c[4], const uint32_t a[4], const uint32_t b[2]) {
    asm volatile(
        "mma.sync.aligned.m16n8k8.row.col.f32.tf32.tf32.f32 "
        "{%0,%1,%2,%3},{%4,%5,%6,%7},{%8,%9},{%0,%1,%2,%3};\n"
        : "+f"(c[0]), "+f"(c[1]), "+f"(c[2]), "+f"(c[3])
        : "r"(a[0]), "r"(a[1]), "r"(a[2]), "r"(a[3]), "r"(b[0]), "r"(b[1]));
}

// ---------------- epilogues ----------------
// 0: QKV scatter (+bias) into g_q / g_k / g_vt
// 3: +bias +res -> out (ldc = DD)
// 4: +bias, QuickGELU -> out (ldc = FFF)
template<int EPI>
__device__ __forceinline__ void do_epi(int r, int c, float v,
                                       const float* __restrict__ bias,
                                       const float* __restrict__ res,
                                       float* __restrict__ out)
{
    if (EPI == 0) {
        v += bias[c];
        int which = c / DD;
        int d = c - which * DD;
        int h = d >> 6, hd = d & 63;
        int b = r >> 10, t = r & 1023;
        int bh = b * HH + h;
        if (which == 0)      g_q [(((size_t)bh << 10) + t) * HDD + hd] = v;
        else if (which == 1) g_k [((size_t)bh * LL + PP + t) * HDD + hd] = v;
        else                 g_vt[((size_t)bh * HDD + hd) * LL + PP + t] = v;
    } else if (EPI == 3) {
        size_t o = (size_t)r * DD + c;
        out[o] = v + bias[c] + res[o];
    } else { // 4
        v += bias[c];
        out[(size_t)r * FFF + c] = v / (1.f + __expf(-1.702f * v));
    }
}

// swizzled smem index for a 16-float-wide tile row
__device__ __forceinline__ int sidx16(int r, int c) {
    return r * 16 + ((((c >> 2) ^ ((r >> 1) & 3))) << 2) + (c & 3);
}

// ---------------- NT GEMM: C = A[M,K] * B[N,K]^T, tf32 mma ----------------
// BM=BN=128, BK=16, 3-stage cp.async pipeline (wait_group 1).
// 256 threads = 8 warps (4m x 2n), warp tile 32x64.
template<int EPI, int ASEL, int RSEL, int OSEL>
__global__ __launch_bounds__(256, 2)
void gemm_nt(const float* __restrict__ Aarg, int lda,
             const float* __restrict__ B, int ldb, int K,
             const float* __restrict__ bias,
             const float* __restrict__ resarg,
             float* __restrict__ outarg)
{
    __shared__ uint32_t As[3][2048];   // 128 x 16 per stage, swizzled
    __shared__ uint32_t Bs[3][2048];

    const float* A   = buf_ptr<ASEL>(Aarg);
    const float* res = buf_ptr<RSEL>(resarg);
    float*       out = buf_ptr<OSEL>(outarg);

    const int tid  = threadIdx.x;
    const int lane = tid & 31, wid = tid >> 5;
    const int warpM = wid >> 1, warpN = wid & 1;
    const int g = lane >> 2, tg = lane & 3;
    const int m0 = blockIdx.y * 128, n0 = blockIdx.x * 128;

    const uint32_t sA = (uint32_t)__cvta_generic_to_shared(&As[0][0]);
    const uint32_t sB = (uint32_t)__cvta_generic_to_shared(&Bs[0][0]);

    // per-thread load coords: 512 float4 per tile, 2 per thread (rows lr, lr+64)
    const int lr  = tid >> 2;
    const int lg  = tid & 3;
    const int lsg = lg ^ ((lr >> 1) & 3);           // same for row lr+64
    const uint32_t aoff = (uint32_t)(lr * 16 + lsg * 4) * 4;

    auto issue = [&](int chunk, int s) {
        const int k0 = chunk << 4;
        const uint32_t so = (uint32_t)(s * 2048) * 4;
        #pragma unroll
        for (int i = 0; i < 2; i++) {
            cp16(sA + so + aoff + (uint32_t)(i * 64 * 16) * 4,
                 A + (size_t)(m0 + lr + i * 64) * lda + k0 + lg * 4);
            cp16(sB + so + aoff + (uint32_t)(i * 64 * 16) * 4,
                 B + (size_t)(n0 + lr + i * 64) * ldb + k0 + lg * 4);
        }
    };

    float acc[2][8][4];
    #pragma unroll
    for (int mt = 0; mt < 2; mt++)
        #pragma unroll
        for (int nt = 0; nt < 8; nt++)
            #pragma unroll
            for (int i = 0; i < 4; i++) acc[mt][nt][i] = 0.f;

    const int chunks = K >> 4;

    issue(0, 0); cp_commit();
    issue(1, 1); cp_commit();

    int s0 = 0, s2 = 2;
    for (int c = 0; c < chunks; c++) {
        cp_wait1();
        __syncthreads();
        if (c + 2 < chunks) issue(c + 2, s2);
        cp_commit();

        const uint32_t* as = As[s0];
        const uint32_t* bs = Bs[s0];
        #pragma unroll
        for (int ks = 0; ks < 2; ks++) {
            const int kk = ks * 8;
            uint32_t a[2][4], b[8][2];
            #pragma unroll
            for (int mt = 0; mt < 2; mt++) {
                int rb = warpM * 32 + mt * 16 + g;
                a[mt][0] = as[sidx16(rb,     kk + tg)];
                a[mt][1] = as[sidx16(rb + 8, kk + tg)];
                a[mt][2] = as[sidx16(rb,     kk + tg + 4)];
                a[mt][3] = as[sidx16(rb + 8, kk + tg + 4)];
            }
            #pragma unroll
            for (int nt = 0; nt < 8; nt++) {
                int cb = warpN * 64 + nt * 8 + g;
                b[nt][0] = bs[sidx16(cb, kk + tg)];
                b[nt][1] = bs[sidx16(cb, kk + tg + 4)];
            }
            #pragma unroll
            for (int mt = 0; mt < 2; mt++)
                #pragma unroll
                for (int nt = 0; nt < 8; nt++)
                    mma_tf32(acc[mt][nt], a[mt], b[nt]);
        }
        s0 = (s0 == 2) ? 0 : s0 + 1;
        s2 = (s2 == 2) ? 0 : s2 + 1;
    }

    // epilogue (all dims are multiples of tile sizes — no guards)
    #pragma unroll
    for (int mt = 0; mt < 2; mt++) {
        #pragma unroll
        for (int nt = 0; nt < 8; nt++) {
            int r0 = m0 + warpM * 32 + mt * 16 + g;
            int c0 = n0 + warpN * 64 + nt * 8 + tg * 2;
            #pragma unroll
            for (int i = 0; i < 4; i++) {
                int r = r0 + (i >> 1) * 8;
                int c = c0 + (i & 1);
                do_epi<EPI>(r, c, acc[mt][nt][i], bias, res, out);
            }
        }
    }
}

// ---------------- fused flash attention (32-key tiles, 3-stage cp.async) ----------------
// grid (8, 192): x = 128-query tile, y = b*H+h. 8 warps, 16 q-rows each.
#define FTILES 33          // ceil(1040/32)
__global__ __launch_bounds__(256)
void flash_kernel()
{
    __shared__ uint32_t Ks[3][32 * 64];   // [key][hd]
    __shared__ uint32_t Vs[3][64 * 32];   // [hd][key]

    const int tid = threadIdx.x, lane = tid & 31, wid = tid >> 5;
    const int g = lane >> 2, tg = lane & 3;
    const int m0 = blockIdx.x * 128;
    const int bh = blockIdx.y;
    const int b = bh / HH, h = bh - b * HH;
    const int wb = wid * 16;

    const uint32_t sK = (uint32_t)__cvta_generic_to_shared(&Ks[0][0]);
    const uint32_t sV = (uint32_t)__cvta_generic_to_shared(&Vs[0][0]);

    // Q fragments straight from gmem (bit-truncated tf32)
    uint32_t qf[8][4];
    {
        const float* Q1 = g_q + ((size_t)bh * NNq + m0 + wb + g) * HDD;
        const float* Q2 = Q1 + 8 * HDD;
        #pragma unroll
        for (int kt = 0; kt < 8; kt++) {
            qf[kt][0] = __float_as_uint(Q1[kt * 8 + tg]);
            qf[kt][1] = __float_as_uint(Q2[kt * 8 + tg]);
            qf[kt][2] = __float_as_uint(Q1[kt * 8 + tg + 4]);
            qf[kt][3] = __float_as_uint(Q2[kt * 8 + tg + 4]);
        }
    }

    float m1 = -1e30f, m2 = -1e30f, l1 = 0.f, l2 = 0.f;
    float oacc[8][4];
    #pragma unroll
    for (int nt = 0; nt < 8; nt++)
        #pragma unroll
        for (int i = 0; i < 4; i++) oacc[nt][i] = 0.f;

    // ---- tile loader ----
    auto issue_tile = [&](int t, int s) {
        const int kb = t * 32;
        const uint32_t soff = (uint32_t)(s * 2048) * 4;
        #pragma unroll
        for (int i = 0; i < 2; i++) {
            int idx = tid + i * 256;
            // K slice
            int kr = idx >> 4, kg = idx & 15;
            int ksg = kg ^ (kr & 7);
            int krow = kb + kr; if (krow >= LL) krow = LL - 1;
            cp16z(sK + soff + (uint32_t)(kr * 64 + ksg * 4) * 4,
                  g_k + ((size_t)bh * LL + krow) * HDD + kg * 4,
                  (kb + kr) < LL ? 16 : 0);
            // V slice
            int vr = idx >> 3, vg = idx & 7;
            int vsg = vg ^ (vr & 7);
            cp16z(sV + soff + (uint32_t)(vr * 32 + vsg * 4) * 4,
                  g_vt + ((size_t)bh * HDD + vr) * LL + kb + vg * 4,
                  (kb + vg * 4 + 4) <= LL ? 16 : 0);
        }
    };

    issue_tile(0, 0); cp_commit();
    issue_tile(1, 1); cp_commit();

    int s0 = 0, s2 = 2;
    for (int t = 0; t < FTILES; t++) {
        const int kb = t * 32;
        cp_wait1();
        __syncthreads();
        if (t + 2 < FTILES) issue_tile(t + 2, s2);
        cp_commit();

        const uint32_t* ks_ = Ks[s0];
        const uint32_t* vs_ = Vs[s0];

        // S = Q K^T  (per-warp 16 x 32)
        float s[4][4];
        #pragma unroll
        for (int nt = 0; nt < 4; nt++)
            #pragma unroll
            for (int i = 0; i < 4; i++) s[nt][i] = 0.f;
        #pragma unroll
        for (int kt = 0; kt < 8; kt++) {
            #pragma unroll
            for (int nt = 0; nt < 4; nt++) {
                int row = nt * 8 + g;
                uint32_t bf[2];
                int c0 = kt * 8 + tg;
                bf[0] = ks_[row * 64 + (((c0 >> 2) ^ (row & 7)) << 2) + tg];
                int c1 = c0 + 4;
                bf[1] = ks_[row * 64 + (((c1 >> 2) ^ (row & 7)) << 2) + tg];
                mma_tf32(s[nt], qf[kt], bf);
            }
        }

        // scale + mask + online softmax
        float mx1 = -1e30f, mx2 = -1e30f;
        #pragma unroll
        for (int nt = 0; nt < 4; nt++) {
            int col = kb + nt * 8 + tg * 2;
            #pragma unroll
            for (int i = 0; i < 4; i++) s[nt][i] *= 0.125f;
            if (col >= LL)     { s[nt][0] = -1e30f; s[nt][2] = -1e30f; }
            if (col + 1 >= LL) { s[nt][1] = -1e30f; s[nt][3] = -1e30f; }
            mx1 = fmaxf(mx1, fmaxf(s[nt][0], s[nt][1]));
            mx2 = fmaxf(mx2, fmaxf(s[nt][2], s[nt][3]));
        }
        #pragma unroll
        for (int o = 1; o <= 2; o <<= 1) {
            mx1 = fmaxf(mx1, __shfl_xor_sync(0xffffffffu, mx1, o));
            mx2 = fmaxf(mx2, __shfl_xor_sync(0xffffffffu, mx2, o));
        }
        const float nm1 = fmaxf(m1, mx1), nm2 = fmaxf(m2, mx2);
        const float f1 = __expf(m1 - nm1), f2 = __expf(m2 - nm2);
        float sum1 = 0.f, sum2 = 0.f;
        #pragma unroll
        for (int nt = 0; nt < 4; nt++) {
            s[nt][0] = __expf(s[nt][0] - nm1); sum1 += s[nt][0];
            s[nt][1] = __expf(s[nt][1] - nm1); sum1 += s[nt][1];
            s[nt][2] = __expf(s[nt][2] - nm2); sum2 += s[nt][2];
            s[nt][3] = __expf(s[nt][3] - nm2); sum2 += s[nt][3];
        }
        #pragma unroll
        for (int o = 1; o <= 2; o <<= 1) {
            sum1 += __shfl_xor_sync(0xffffffffu, sum1, o);
            sum2 += __shfl_xor_sync(0xffffffffu, sum2, o);
        }
        l1 = l1 * f1 + sum1; m1 = nm1;
        l2 = l2 * f2 + sum2; m2 = nm2;
        #pragma unroll
        for (int nt = 0; nt < 8; nt++) {
            oacc[nt][0] *= f1; oacc[nt][1] *= f1;
            oacc[nt][2] *= f2; oacc[nt][3] *= f2;
        }

        // P * V : C-fragment -> A-fragment via shuffles (4 k8 chunks)
        const int src_a = g * 4 + (tg >> 1);
        const int src_b = src_a + 2;
        const int sel = tg & 1;
        #pragma unroll
        for (int kt = 0; kt < 4; kt++) {
            uint32_t p0 = __float_as_uint(s[kt][0]);
            uint32_t p1 = __float_as_uint(s[kt][1]);
            uint32_t p2 = __float_as_uint(s[kt][2]);
            uint32_t p3 = __float_as_uint(s[kt][3]);
            uint32_t x0 = __shfl_sync(0xffffffffu, p0, src_a);
            uint32_t x1 = __shfl_sync(0xffffffffu, p1, src_a);
            uint32_t x2 = __shfl_sync(0xffffffffu, p2, src_a);
            uint32_t x3 = __shfl_sync(0xffffffffu, p3, src_a);
            uint32_t y0 = __shfl_sync(0xffffffffu, p0, src_b);
            uint32_t y1 = __shfl_sync(0xffffffffu, p1, src_b);
            uint32_t y2 = __shfl_sync(0xffffffffu, p2, src_b);
            uint32_t y3 = __shfl_sync(0xffffffffu, p3, src_b);
            uint32_t af[4];
            af[0] = sel ? x1 : x0;
            af[1] = sel ? x3 : x2;
            af[2] = sel ? y1 : y0;
            af[3] = sel ? y3 : y2;
            #pragma unroll
            for (int nt = 0; nt < 8; nt++) {
                int row = nt * 8 + g;
                uint32_t bf[2];
                int c0 = kt * 8 + tg;
                bf[0] = vs_[row * 32 + (((c0 >> 2) ^ (row & 7)) << 2) + tg];
                int c1 = c0 + 4;
                bf[1] = vs_[row * 32 + (((c1 >> 2) ^ (row & 7)) << 2) + tg];
                mma_tf32(oacc[nt], af, bf);
            }
        }
        s0 = (s0 == 2) ? 0 : s0 + 1;
        s2 = (s2 == 2) ? 0 : s2 + 1;
    }

    // epilogue: normalize and store to g_o [b,t, h*64+hd]
    const float inv1 = 1.f / l1, inv2 = 1.f / l2;
    float* O1 = g_o + ((size_t)(b * NNq) + m0 + wb + g) * DD + h * HDD;
    float* O2 = O1 + 8 * DD;
    #pragma unroll
    for (int nt = 0; nt < 8; nt++) {
        int c = nt * 8 + tg * 2;
        O1[c]     = oacc[nt][0] * inv1;
        O1[c + 1] = oacc[nt][1] * inv1;
        O2[c]     = oacc[nt][2] * inv2;
        O2[c + 1] = oacc[nt][3] * inv2;
    }
}

// ---------------- LayerNorm (one block per token; out -> g_h) ----------------
template<int XSEL>
__global__ __launch_bounds__(256)
void ln_kernel(const float* __restrict__ xarg, const float* __restrict__ gw,
               const float* __restrict__ bw)
{
    __shared__ float red[2][8];
    __shared__ float s_mu, s_rstd;
    const float* x = buf_ptr<XSEL>(xarg);
    const int row = blockIdx.x;
    const float* xr = x + (size_t)row * DD;
    float* orow = g_h + (size_t)row * DD;
    const int tid = threadIdx.x;

    float lv[3];
    float s = 0.f, s2 = 0.f;
    #pragma unroll
    for (int i = 0; i < 3; i++) {
        float v = xr[tid + i * 256];
        lv[i] = v; s += v; s2 += v * v;
    }
    #pragma unroll
    for (int o = 16; o; o >>= 1) {
        s  += __shfl_xor_sync(0xffffffffu, s,  o);
        s2 += __shfl_xor_sync(0xffffffffu, s2, o);
    }
    if ((tid & 31) == 0) { red[0][tid >> 5] = s; red[1][tid >> 5] = s2; }
    __syncthreads();
    if (tid == 0) {
        float ts = 0.f, ts2 = 0.f;
        #pragma unroll
        for (int i = 0; i < 8; i++) { ts += red[0][i]; ts2 += red[1][i]; }
        float mu = ts * (1.f / 768.f);
        float var = ts2 * (1.f / 768.f) - mu * mu;
        s_mu = mu; s_rstd = rsqrtf(var + 1e-5f);
    }
    __syncthreads();
    const float mu = s_mu, rstd = s_rstd;
    #pragma unroll
    for (int i = 0; i < 3; i++) {
        int c = tid + i * 256;
        orow[c] = (lv[i] - mu) * rstd * gw[c] + bw[c];
    }
}

// ---------------- prompt scatter: prompt[B,2,P,H,HD] -> g_k / g_vt ----------------
__global__ __launch_bounds__(256)
void prompt_copy(const float* __restrict__ pr)
{
    int idx = blockIdx.x * 256 + threadIdx.x;
    if (idx >= BB * 2 * PP * HH * HDD) return;
    float v = pr[idx];
    int hd = idx & 63; int t = idx >> 6;
    int h = t % HH;    t /= HH;
    int p = t % PP;    t /= PP;
    int kv = t & 1;    int b = t >> 1;
    int bh = b * HH + h;
    if (kv == 0) g_k [((size_t)bh * LL + p) * HDD + hd] = v;
    else         g_vt[((size_t)bh * HDD + hd) * LL + p] = v;
}

// ---------------- launcher (kernel launches ONLY) ----------------
extern "C" void kernel_launch(void* const* d_in, const int* in_sizes, int n_in,
                              void* d_out, int out_size)
{
    const float* x      = (const float*)d_in[0];
    const float* prompt = (const float*)d_in[1];
    const float* qkv_w  = (const float*)d_in[2];
    const float* qkv_b  = (const float*)d_in[3];
    const float* out_w  = (const float*)d_in[4];
    const float* out_b  = (const float*)d_in[5];
    const float* ln1_g  = (const float*)d_in[6];
    const float* ln1_b  = (const float*)d_in[7];
    const float* ln2_g  = (const float*)d_in[8];
    const float* ln2_b  = (const float*)d_in[9];
    const float* fc1_w  = (const float*)d_in[10];
    const float* fc1_b  = (const float*)d_in[11];
    const float* fc2_w  = (const float*)d_in[12];
    const float* fc2_b  = (const float*)d_in[13];
    float* outp = (float*)d_out;

    // 1. prompt scatter into K / V^T caches
    prompt_copy<<<(BB * 2 * PP * HH * HDD + 255) / 256, 256>>>(prompt);
    // 2. LN1: x -> g_h
    ln_kernel<0><<<MTOK, 256>>>(x, ln1_g, ln1_b);
    // 3. QKV GEMM + scatter into g_q / g_k / g_vt
    gemm_nt<0, 1, 0, 0><<<dim3(18, 128), 256>>>(
        nullptr, DD, qkv_w, DD, DD, qkv_b, nullptr, nullptr);
    // 4. fused flash attention -> g_o
    flash_kernel<<<dim3(8, BHh), 256>>>();
    // 5. out-proj + bias + residual(x) -> g_x1
    gemm_nt<3, 2, 0, 3><<<dim3(6, 128), 256>>>(
        nullptr, DD, out_w, DD, DD, out_b, x, nullptr);
    // 6. LN2: g_x1 -> g_h
    ln_kernel<3><<<MTOK, 256>>>(nullptr, ln2_g, ln2_b);
    // 7. FC1 + bias + QuickGELU -> g_m
    gemm_nt<4, 1, 0, 4><<<dim3(24, 128), 256>>>(
        nullptr, DD, fc1_w, DD, DD, fc1_b, nullptr, nullptr);
    // 8. FC2 + bias + residual(g_x1) -> d_out
    gemm_nt<3, 4, 3, 0><<<dim3(6, 128), 256>>>(
        nullptr, FFF, fc2_w, FFF, FFF, fc2_b, nullptr, outp);
}

// round 6
// speedup vs baseline: 1.7692x; 1.3333x over previous
#include <cuda_runtime.h>
#include <cstdint>
#include <cstddef>

// ---------------- problem constants ----------------
#define BB   16
#define NNq  1024
#define DD   768
#define HH   12
#define HDD  64
#define PP   16
#define FFF  3072
#define MTOK (BB*NNq)     // 16384
#define LL   (PP+NNq)     // 1040
#define BHh  (BB*HH)      // 192

// ---------------- scratch (device globals; no allocation) ----------------
__device__ float g_h [MTOK*DD];
__device__ float g_q [BHh*NNq*HDD];
__device__ float g_k [BHh*LL*HDD];
__device__ float g_vt[BHh*HDD*LL];
__device__ float g_o [MTOK*DD];
__device__ float g_x1[MTOK*DD];
__device__ float g_m [MTOK*FFF];

template<int SEL>
__device__ __forceinline__ float* buf_ptr(const void* arg) {
    if (SEL == 1) return g_h;
    if (SEL == 2) return g_o;
    if (SEL == 3) return g_x1;
    if (SEL == 4) return g_m;
    return (float*)arg;
}

// ---------------- async-copy / mma helpers ----------------
__device__ __forceinline__ void cp16(uint32_t d, const void* s) {
    asm volatile("cp.async.cg.shared.global [%0], [%1], 16;\n" :: "r"(d), "l"(s));
}
__device__ __forceinline__ void cp16z(uint32_t d, const void* s, int sz) {
    asm volatile("cp.async.cg.shared.global [%0], [%1], 16, %2;\n" :: "r"(d), "l"(s), "r"(sz));
}
__device__ __forceinline__ void cp_commit() { asm volatile("cp.async.commit_group;\n" ::: "memory"); }
__device__ __forceinline__ void cp_wait1()  { asm volatile("cp.async.wait_group 1;\n" ::: "memory"); }

__device__ __forceinline__ void mma_tf32(float c[4], const uint32_t a[4], const uint32_t b[2]) {
    asm volatile(
        "mma.sync.aligned.m16n8k8.row.col.f32.tf32.tf32.f32 "
        "{%0,%1,%2,%3},{%4,%5,%6,%7},{%8,%9},{%0,%1,%2,%3};\n"
        : "+f"(c[0]), "+f"(c[1]), "+f"(c[2]), "+f"(c[3])
        : "r"(a[0]), "r"(a[1]), "r"(a[2]), "r"(a[3]), "r"(b[0]), "r"(b[1]));
}

// ldmatrix x4 (b16 view): for tf32, each fetched 16B row = 4 tf32 elements;
// lane i of each 8-lane group receives element (row i/4, col i%4) -> exact
// m16n8k8 tf32 fragment layout.
__device__ __forceinline__ void ldsm4(uint32_t r[4], uint32_t addr) {
    asm volatile("ldmatrix.sync.aligned.m8n8.x4.shared.b16 {%0,%1,%2,%3}, [%4];\n"
        : "=r"(r[0]), "=r"(r[1]), "=r"(r[2]), "=r"(r[3]) : "r"(addr));
}

// ---------------- epilogues ----------------
template<int EPI>
__device__ __forceinline__ void do_epi(int r, int c, float v,
                                       const float* __restrict__ bias,
                                       const float* __restrict__ res,
                                       float* __restrict__ out)
{
    if (EPI == 0) {
        v += bias[c];
        int which = c / DD;
        int d = c - which * DD;
        int h = d >> 6, hd = d & 63;
        int b = r >> 10, t = r & 1023;
        int bh = b * HH + h;
        if (which == 0)      g_q [(((size_t)bh << 10) + t) * HDD + hd] = v;
        else if (which == 1) g_k [((size_t)bh * LL + PP + t) * HDD + hd] = v;
        else                 g_vt[((size_t)bh * HDD + hd) * LL + PP + t] = v;
    } else if (EPI == 3) {
        size_t o = (size_t)r * DD + c;
        out[o] = v + bias[c] + res[o];
    } else { // 4
        v += bias[c];
        out[(size_t)r * FFF + c] = v / (1.f + __expf(-1.702f * v));
    }
}

// ---------------- NT GEMM: C = A[M,K] * B[N,K]^T, tf32 mma + LDSM ----------------
// BM=BN=128, BK=16, 3-stage cp.async pipeline (wait_group 1).
// 256 threads = 8 warps (4m x 2n), warp tile 32x64.
template<int EPI, int ASEL, int RSEL, int OSEL>
__global__ __launch_bounds__(256, 2)
void gemm_nt(const float* __restrict__ Aarg, int lda,
             const float* __restrict__ B, int ldb, int K,
             const float* __restrict__ bias,
             const float* __restrict__ resarg,
             float* __restrict__ outarg)
{
    __shared__ uint32_t As[3][2048];   // 128 x 16 per stage, XOR-swizzled 16B groups
    __shared__ uint32_t Bs[3][2048];

    const float* A   = buf_ptr<ASEL>(Aarg);
    const float* res = buf_ptr<RSEL>(resarg);
    float*       out = buf_ptr<OSEL>(outarg);

    const int tid  = threadIdx.x;
    const int lane = tid & 31, wid = tid >> 5;
    const int warpM = wid >> 1, warpN = wid & 1;
    const int g = lane >> 2, tg = lane & 3;
    const int m0 = blockIdx.y * 128, n0 = blockIdx.x * 128;

    const uint32_t sA = (uint32_t)__cvta_generic_to_shared(&As[0][0]);
    const uint32_t sB = (uint32_t)__cvta_generic_to_shared(&Bs[0][0]);

    // cp.async coords (512 float4 per tile, 2 per thread: rows lr, lr+64)
    const int lr  = tid >> 2;
    const int lg  = tid & 3;
    const int lsg = lg ^ ((lr >> 1) & 3);
    const uint32_t aoff = (uint32_t)(lr * 16 + lsg * 4) * 4;

    auto issue = [&](int chunk, int s) {
        const int k0 = chunk << 4;
        const uint32_t so = (uint32_t)(s * 2048) * 4;
        #pragma unroll
        for (int i = 0; i < 2; i++) {
            cp16(sA + so + aoff + (uint32_t)(i * 64 * 16) * 4,
                 A + (size_t)(m0 + lr + i * 64) * lda + k0 + lg * 4);
            cp16(sB + so + aoff + (uint32_t)(i * 64 * 16) * 4,
                 B + (size_t)(n0 + lr + i * 64) * ldb + k0 + lg * 4);
        }
    };

    // ldmatrix per-lane in-tile byte offsets (hoisted out of K loop)
    // A x4 for mt: mat m: row = base + (m&1)*8 + Lr, colgroup = ks*2 + (m>>1)
    // B x4 for nt-pair np: mat m: row = base + (m>>1)*8 + Lr, colgroup = ks*2 + (m&1)
    const int Lm = lane >> 3, Lr = lane & 7;
    uint32_t aoffm[2][2], boffm[4][2];
    #pragma unroll
    for (int mt = 0; mt < 2; mt++)
        #pragma unroll
        for (int ks = 0; ks < 2; ks++) {
            int row = warpM * 32 + mt * 16 + ((Lm & 1) << 3) + Lr;
            int cg  = (ks << 1) + (Lm >> 1);
            aoffm[mt][ks] = (uint32_t)(row * 64 + (((cg ^ ((row >> 1) & 3))) << 4));
        }
    #pragma unroll
    for (int np = 0; np < 4; np++)
        #pragma unroll
        for (int ks = 0; ks < 2; ks++) {
            int row = warpN * 64 + np * 16 + ((Lm >> 1) << 3) + Lr;
            int cg  = (ks << 1) + (Lm & 1);
            boffm[np][ks] = (uint32_t)(row * 64 + (((cg ^ ((row >> 1) & 3))) << 4));
        }

    float acc[2][8][4];
    #pragma unroll
    for (int mt = 0; mt < 2; mt++)
        #pragma unroll
        for (int nt = 0; nt < 8; nt++)
            #pragma unroll
            for (int i = 0; i < 4; i++) acc[mt][nt][i] = 0.f;

    const int chunks = K >> 4;
    issue(0, 0); cp_commit();
    issue(1, 1); cp_commit();

    int s0 = 0, s2 = 2;
    for (int c = 0; c < chunks; c++) {
        cp_wait1();
        __syncthreads();
        if (c + 2 < chunks) issue(c + 2, s2);
        cp_commit();

        const uint32_t so = (uint32_t)(s0 * 2048) * 4;
        #pragma unroll
        for (int ks = 0; ks < 2; ks++) {
            uint32_t a[2][4], b[8][2];
            ldsm4(a[0], sA + so + aoffm[0][ks]);
            ldsm4(a[1], sA + so + aoffm[1][ks]);
            #pragma unroll
            for (int np = 0; np < 4; np++) {
                uint32_t t4[4];
                ldsm4(t4, sB + so + boffm[np][ks]);
                b[2*np][0]   = t4[0]; b[2*np][1]   = t4[1];
                b[2*np+1][0] = t4[2]; b[2*np+1][1] = t4[3];
            }
            #pragma unroll
            for (int mt = 0; mt < 2; mt++)
                #pragma unroll
                for (int nt = 0; nt < 8; nt++)
                    mma_tf32(acc[mt][nt], a[mt], b[nt]);
        }
        s0 = (s0 == 2) ? 0 : s0 + 1;
        s2 = (s2 == 2) ? 0 : s2 + 1;
    }

    #pragma unroll
    for (int mt = 0; mt < 2; mt++) {
        #pragma unroll
        for (int nt = 0; nt < 8; nt++) {
            int r0 = m0 + warpM * 32 + mt * 16 + g;
            int c0 = n0 + warpN * 64 + nt * 8 + tg * 2;
            #pragma unroll
            for (int i = 0; i < 4; i++) {
                int r = r0 + (i >> 1) * 8;
                int c = c0 + (i & 1);
                do_epi<EPI>(r, c, acc[mt][nt][i], bias, res, out);
            }
        }
    }
}

// ---------------- fused flash attention (32-key tiles, 3-stage cp.async, LDSM) ----------------
#define FTILES 33          // ceil(1040/32)
__global__ __launch_bounds__(256, 2)
void flash_kernel()
{
    __shared__ uint32_t Ks[3][32 * 64];   // [key][hd], 16B groups swizzled by ^(row&7)
    __shared__ uint32_t Vs[3][64 * 32];   // [hd][key]

    const int tid = threadIdx.x, lane = tid & 31, wid = tid >> 5;
    const int g = lane >> 2, tg = lane & 3;
    const int m0 = blockIdx.x * 128;
    const int bh = blockIdx.y;
    const int b = bh / HH, h = bh - b * HH;
    const int wb = wid * 16;

    const uint32_t sK = (uint32_t)__cvta_generic_to_shared(&Ks[0][0]);
    const uint32_t sV = (uint32_t)__cvta_generic_to_shared(&Vs[0][0]);

    // Q fragments straight from gmem (bit-truncated tf32)
    uint32_t qf[8][4];
    {
        const float* Q1 = g_q + ((size_t)bh * NNq + m0 + wb + g) * HDD;
        const float* Q2 = Q1 + 8 * HDD;
        #pragma unroll
        for (int kt = 0; kt < 8; kt++) {
            qf[kt][0] = __float_as_uint(Q1[kt * 8 + tg]);
            qf[kt][1] = __float_as_uint(Q2[kt * 8 + tg]);
            qf[kt][2] = __float_as_uint(Q1[kt * 8 + tg + 4]);
            qf[kt][3] = __float_as_uint(Q2[kt * 8 + tg + 4]);
        }
    }

    // ldmatrix per-lane row bases
    const int Lm = lane >> 3, Lr = lane & 7;
    const int cgsel = Lm & 1;
    uint32_t krb[2]; int krm[2];
    #pragma unroll
    for (int np = 0; np < 2; np++) {
        int row = np * 16 + ((Lm >> 1) << 3) + Lr;    // K tile row (key)
        krb[np] = (uint32_t)(row * 256);              // 64 floats/row
        krm[np] = row & 7;
    }
    uint32_t vrb[4]; int vrm[4];
    #pragma unroll
    for (int np = 0; np < 4; np++) {
        int row = np * 16 + ((Lm >> 1) << 3) + Lr;    // V tile row (hd)
        vrb[np] = (uint32_t)(row * 128);              // 32 floats/row
        vrm[np] = row & 7;
    }

    float m1 = -1e30f, m2 = -1e30f, l1 = 0.f, l2 = 0.f;
    float oacc[8][4];
    #pragma unroll
    for (int nt = 0; nt < 8; nt++)
        #pragma unroll
        for (int i = 0; i < 4; i++) oacc[nt][i] = 0.f;

    auto issue_tile = [&](int t, int s) {
        const int kb = t * 32;
        const uint32_t soff = (uint32_t)(s * 2048) * 4;
        #pragma unroll
        for (int i = 0; i < 2; i++) {
            int idx = tid + i * 256;
            int kr = idx >> 4, kg = idx & 15;
            int ksg = kg ^ (kr & 7);
            int krow = kb + kr; if (krow >= LL) krow = LL - 1;
            cp16z(sK + soff + (uint32_t)(kr * 64 + ksg * 4) * 4,
                  g_k + ((size_t)bh * LL + krow) * HDD + kg * 4,
                  (kb + kr) < LL ? 16 : 0);
            int vr = idx >> 3, vg = idx & 7;
            int vsg = vg ^ (vr & 7);
            cp16z(sV + soff + (uint32_t)(vr * 32 + vsg * 4) * 4,
                  g_vt + ((size_t)bh * HDD + vr) * LL + kb + vg * 4,
                  (kb + vg * 4 + 4) <= LL ? 16 : 0);
        }
    };

    issue_tile(0, 0); cp_commit();
    issue_tile(1, 1); cp_commit();

    int s0 = 0, s2 = 2;
    for (int t = 0; t < FTILES; t++) {
        const int kb = t * 32;
        cp_wait1();
        __syncthreads();
        if (t + 2 < FTILES) issue_tile(t + 2, s2);
        cp_commit();

        const uint32_t soK = sK + (uint32_t)(s0 * 2048) * 4;
        const uint32_t soV = sV + (uint32_t)(s0 * 2048) * 4;

        // S = Q K^T  (per-warp 16 x 32)
        float s[4][4];
        #pragma unroll
        for (int nt = 0; nt < 4; nt++)
            #pragma unroll
            for (int i = 0; i < 4; i++) s[nt][i] = 0.f;
        #pragma unroll
        for (int kt = 0; kt < 8; kt++) {
            #pragma unroll
            for (int np = 0; np < 2; np++) {
                uint32_t t4[4];
                ldsm4(t4, soK + krb[np] + (uint32_t)((((kt << 1) | cgsel) ^ krm[np]) << 4));
                mma_tf32(s[np*2],     qf[kt], &t4[0]);
                mma_tf32(s[np*2 + 1], qf[kt], &t4[2]);
            }
        }

        // scale + mask + online softmax
        float mx1 = -1e30f, mx2 = -1e30f;
        #pragma unroll
        for (int nt = 0; nt < 4; nt++) {
            int col = kb + nt * 8 + tg * 2;
            #pragma unroll
            for (int i = 0; i < 4; i++) s[nt][i] *= 0.125f;
            if (col >= LL)     { s[nt][0] = -1e30f; s[nt][2] = -1e30f; }
            if (col + 1 >= LL) { s[nt][1] = -1e30f; s[nt][3] = -1e30f; }
            mx1 = fmaxf(mx1, fmaxf(s[nt][0], s[nt][1]));
            mx2 = fmaxf(mx2, fmaxf(s[nt][2], s[nt][3]));
        }
        #pragma unroll
        for (int o = 1; o <= 2; o <<= 1) {
            mx1 = fmaxf(mx1, __shfl_xor_sync(0xffffffffu, mx1, o));
            mx2 = fmaxf(mx2, __shfl_xor_sync(0xffffffffu, mx2, o));
        }
        const float nm1 = fmaxf(m1, mx1), nm2 = fmaxf(m2, mx2);
        const float f1 = __expf(m1 - nm1), f2 = __expf(m2 - nm2);
        float sum1 = 0.f, sum2 = 0.f;
        #pragma unroll
        for (int nt = 0; nt < 4; nt++) {
            s[nt][0] = __expf(s[nt][0] - nm1); sum1 += s[nt][0];
            s[nt][1] = __expf(s[nt][1] - nm1); sum1 += s[nt][1];
            s[nt][2] = __expf(s[nt][2] - nm2); sum2 += s[nt][2];
            s[nt][3] = __expf(s[nt][3] - nm2); sum2 += s[nt][3];
        }
        #pragma unroll
        for (int o = 1; o <= 2; o <<= 1) {
            sum1 += __shfl_xor_sync(0xffffffffu, sum1, o);
            sum2 += __shfl_xor_sync(0xffffffffu, sum2, o);
        }
        l1 = l1 * f1 + sum1; m1 = nm1;
        l2 = l2 * f2 + sum2; m2 = nm2;
        #pragma unroll
        for (int nt = 0; nt < 8; nt++) {
            oacc[nt][0] *= f1; oacc[nt][1] *= f1;
            oacc[nt][2] *= f2; oacc[nt][3] *= f2;
        }

        // P * V : C-fragment -> A-fragment via shuffles (4 k8 chunks)
        const int src_a = g * 4 + (tg >> 1);
        const int src_b = src_a + 2;
        const int sel = tg & 1;
        #pragma unroll
        for (int kt = 0; kt < 4; kt++) {
            uint32_t p0 = __float_as_uint(s[kt][0]);
            uint32_t p1 = __float_as_uint(s[kt][1]);
            uint32_t p2 = __float_as_uint(s[kt][2]);
            uint32_t p3 = __float_as_uint(s[kt][3]);
            uint32_t x0 = __shfl_sync(0xffffffffu, p0, src_a);
            uint32_t x1 = __shfl_sync(0xffffffffu, p1, src_a);
            uint32_t x2 = __shfl_sync(0xffffffffu, p2, src_a);
            uint32_t x3 = __shfl_sync(0xffffffffu, p3, src_a);
            uint32_t y0 = __shfl_sync(0xffffffffu, p0, src_b);
            uint32_t y1 = __shfl_sync(0xffffffffu, p1, src_b);
            uint32_t y2 = __shfl_sync(0xffffffffu, p2, src_b);
            uint32_t y3 = __shfl_sync(0xffffffffu, p3, src_b);
            uint32_t af[4];
            af[0] = sel ? x1 : x0;
            af[1] = sel ? x3 : x2;
            af[2] = sel ? y1 : y0;
            af[3] = sel ? y3 : y2;
            #pragma unroll
            for (int np = 0; np < 4; np++) {
                uint32_t t4[4];
                ldsm4(t4, soV + vrb[np] + (uint32_t)((((kt << 1) | cgsel) ^ vrm[np]) << 4));
                mma_tf32(oacc[np*2],     af, &t4[0]);
                mma_tf32(oacc[np*2 + 1], af, &t4[2]);
            }
        }
        s0 = (s0 == 2) ? 0 : s0 + 1;
        s2 = (s2 == 2) ? 0 : s2 + 1;
    }

    // epilogue: normalize and store to g_o [b,t, h*64+hd]
    const float inv1 = 1.f / l1, inv2 = 1.f / l2;
    float* O1 = g_o + ((size_t)(b * NNq) + m0 + wb + g) * DD + h * HDD;
    float* O2 = O1 + 8 * DD;
    #pragma unroll
    for (int nt = 0; nt < 8; nt++) {
        int c = nt * 8 + tg * 2;
        O1[c]     = oacc[nt][0] * inv1;
        O1[c + 1] = oacc[nt][1] * inv1;
        O2[c]     = oacc[nt][2] * inv2;
        O2[c + 1] = oacc[nt][3] * inv2;
    }
}

// ---------------- LayerNorm (one block per token; out -> g_h) ----------------
template<int XSEL>
__global__ __launch_bounds__(256)
void ln_kernel(const float* __restrict__ xarg, const float* __restrict__ gw,
               const float* __restrict__ bw)
{
    __shared__ float red[2][8];
    __shared__ float s_mu, s_rstd;
    const float* x = buf_ptr<XSEL>(xarg);
    const int row = blockIdx.x;
    const float* xr = x + (size_t)row * DD;
    float* orow = g_h + (size_t)row * DD;
    const int tid = threadIdx.x;

    float lv[3];
    float s = 0.f, s2 = 0.f;
    #pragma unroll
    for (int i = 0; i < 3; i++) {
        float v = xr[tid + i * 256];
        lv[i] = v; s += v; s2 += v * v;
    }
    #pragma unroll
    for (int o = 16; o; o >>= 1) {
        s  += __shfl_xor_sync(0xffffffffu, s,  o);
        s2 += __shfl_xor_sync(0xffffffffu, s2, o);
    }
    if ((tid & 31) == 0) { red[0][tid >> 5] = s; red[1][tid >> 5] = s2; }
    __syncthreads();
    if (tid == 0) {
        float ts = 0.f, ts2 = 0.f;
        #pragma unroll
        for (int i = 0; i < 8; i++) { ts += red[0][i]; ts2 += red[1][i]; }
        float mu = ts * (1.f / 768.f);
        float var = ts2 * (1.f / 768.f) - mu * mu;
        s_mu = mu; s_rstd = rsqrtf(var + 1e-5f);
    }
    __syncthreads();
    const float mu = s_mu, rstd = s_rstd;
    #pragma unroll
    for (int i = 0; i < 3; i++) {
        int c = tid + i * 256;
        orow[c] = (lv[i] - mu) * rstd * gw[c] + bw[c];
    }
}

// ---------------- prompt scatter ----------------
__global__ __launch_bounds__(256)
void prompt_copy(const float* __restrict__ pr)
{
    int idx = blockIdx.x * 256 + threadIdx.x;
    if (idx >= BB * 2 * PP * HH * HDD) return;
    float v = pr[idx];
    int hd = idx & 63; int t = idx >> 6;
    int h = t % HH;    t /= HH;
    int p = t % PP;    t /= PP;
    int kv = t & 1;    int b = t >> 1;
    int bh = b * HH + h;
    if (kv == 0) g_k [((size_t)bh * LL + p) * HDD + hd] = v;
    else         g_vt[((size_t)bh * HDD + hd) * LL + p] = v;
}

// ---------------- launcher (kernel launches ONLY) ----------------
extern "C" void kernel_launch(void* const* d_in, const int* in_sizes, int n_in,
                              void* d_out, int out_size)
{
    const float* x      = (const float*)d_in[0];
    const float* prompt = (const float*)d_in[1];
    const float* qkv_w  = (const float*)d_in[2];
    const float* qkv_b  = (const float*)d_in[3];
    const float* out_w  = (const float*)d_in[4];
    const float* out_b  = (const float*)d_in[5];
    const float* ln1_g  = (const float*)d_in[6];
    const float* ln1_b  = (const float*)d_in[7];
    const float* ln2_g  = (const float*)d_in[8];
    const float* ln2_b  = (const float*)d_in[9];
    const float* fc1_w  = (const float*)d_in[10];
    const float* fc1_b  = (const float*)d_in[11];
    const float* fc2_w  = (const float*)d_in[12];
    const float* fc2_b  = (const float*)d_in[13];
    float* outp = (float*)d_out;

    prompt_copy<<<(BB * 2 * PP * HH * HDD + 255) / 256, 256>>>(prompt);
    ln_kernel<0><<<MTOK, 256>>>(x, ln1_g, ln1_b);
    gemm_nt<0, 1, 0, 0><<<dim3(18, 128), 256>>>(
        nullptr, DD, qkv_w, DD, DD, qkv_b, nullptr, nullptr);
    flash_kernel<<<dim3(8, BHh), 256>>>();
    gemm_nt<3, 2, 0, 3><<<dim3(6, 128), 256>>>(
        nullptr, DD, out_w, DD, DD, out_b, x, nullptr);
    ln_kernel<3><<<MTOK, 256>>>(nullptr, ln2_g, ln2_b);
    gemm_nt<4, 1, 0, 4><<<dim3(24, 128), 256>>>(
        nullptr, DD, fc1_w, DD, DD, fc1_b, nullptr, nullptr);
    gemm_nt<3, 4, 3, 0><<<dim3(6, 128), 256>>>(
        nullptr, FFF, fc2_w, FFF, FFF, fc2_b, nullptr, outp);
}